// round 2
// baseline (speedup 1.0000x reference)
#include <cuda_runtime.h>
#include <cstdint>
#include <cstring>

// ============================================================================
// Sparse masked CNN pyramid (14 levels) + MLP head — round 2.
//   build_all0 : levels 0..7 index maps + compaction, one launch (256 blocks)
//   build_top  : levels 8..13, one block
//   conv1      : 5x5, cin=1 -> 32 at active pixels
//   convk      : 3x3 stride-2, 32->32 sparse tile-GEMM, f32x2 packed FFMA
//   tail       : levels 8..13 convs + pools + MLP, one block
// ============================================================================

#define CAP 131072
#define NLEV 14
#define IDX_TOTAL 5592407

__device__ __align__(16) float g_FA[CAP * 32];
__device__ __align__(16) float g_FB[CAP * 32];
__device__ int   g_idx[IDX_TOTAL];
__device__ int   g_pos[NLEV * CAP];
__device__ int   g_cnt[NLEV];
__device__ float g_pools[NLEV * 32];

__constant__ int c_LS[NLEV]   = {2048,1024,512,256,128,64,32,16,8,4,2,1,1,1};
__constant__ int c_IOFS[NLEV] = {0,4194304,5242880,5505024,5570560,5586944,5591040,
                                 5592064,5592320,5592384,5592400,5592404,5592405,5592406};

// ---- packed f32x2 FMA ------------------------------------------------------
#define FMA2(d, a, b, c) \
    asm("fma.rn.f32x2 %0, %1, %2, %3;" : "=l"(d) : "l"(a), "l"(b), "l"(c))

__device__ __forceinline__ float2 upk(unsigned long long a) {
    float2 f; memcpy(&f, &a, 8); return f;
}

// ---- block compaction step (1024-thread blocks only) -----------------------
// act: predicate; lin: linear cell index within the level map (-1 = no cell);
// posword: (i<<16)|j; bitdst: optional, lane0 of each warp writes its ballot.
__device__ __forceinline__ void emit(int level, bool act, int lin, int posword,
                                     int iofs, unsigned* bitdst) {
    __shared__ int ewcnt[32];
    __shared__ int ewbase[32];
    __shared__ int ebbase;
    int tid = threadIdx.x, wid = tid >> 5, lane = tid & 31;
    unsigned m = __ballot_sync(0xffffffffu, act);
    if (lane == 0) {
        ewcnt[wid] = __popc(m);
        if (bitdst) bitdst[wid] = m;
    }
    __syncthreads();
    if (tid < 32) {
        int cc = ewcnt[tid];
        int x = cc;
        #pragma unroll
        for (int o = 1; o < 32; o <<= 1) {
            int y = __shfl_up_sync(0xffffffffu, x, o);
            if (tid >= o) x += y;
        }
        ewbase[tid] = x - cc;
        if (tid == 31) ebbase = atomicAdd(&g_cnt[level], x);
    }
    __syncthreads();
    int idx = -1;
    if (act) {
        idx = ebbase + ewbase[wid] + __popc(m & ((1u << lane) - 1u));
        if (idx < CAP) g_pos[level * CAP + idx] = posword;
        else idx = -1;
    }
    if (lin >= 0) g_idx[iofs + lin] = idx;
    __syncthreads();
}

__device__ __forceinline__ int getbit(const unsigned* a, int c) {
    return (a[c >> 5] >> (c & 31)) & 1;
}

// ---- levels 0..7 in one kernel: block = 128x128 base tile ------------------
__global__ __launch_bounds__(1024) void build_all0(const float* __restrict__ mask) {
    __shared__ unsigned a0[512];   // 16384 bits (level-0 activity, tile-local)
    __shared__ unsigned a1[128];   // 4096 bits
    __shared__ unsigned a2[32];
    __shared__ unsigned a3[8];
    __shared__ unsigned a4[32];    // padded to warp-count writes
    __shared__ unsigned a5[32];
    __shared__ unsigned a6[32];
    int tid = threadIdx.x;
    int tx = blockIdx.x & 15, ty = blockIdx.x >> 4;

    // level 0: 16 chunks of 1024 cells
    for (int r = 0; r < 16; r++) {
        int c = r * 1024 + tid;
        int li = c >> 7, lj = c & 127;
        int i = ty * 128 + li, j = tx * 128 + lj;
        bool act = (mask[i * 2048 + j] != 0.0f);
        emit(0, act, i * 2048 + j, (i << 16) | j, c_IOFS[0], a0 + r * 32);
    }
    // levels 1..7
    unsigned* bits[8] = {a0, a1, a2, a3, a4, a5, a6, nullptr};
    #pragma unroll
    for (int L = 1; L <= 7; L++) {
        int t = 128 >> L;              // cells per tile side
        int cells = t * t;
        int chunks = (cells + 1023) >> 10;
        int tprev = t * 2;
        for (int r = 0; r < chunks; r++) {
            int c = r * 1024 + tid;
            bool act = false;
            int lin = -1, pw = 0;
            if (c < cells) {
                int li = c / t, lj = c - li * t;
                int c00 = (2 * li) * tprev + 2 * lj;
                const unsigned* pb = bits[L - 1];
                act = getbit(pb, c00) | getbit(pb, c00 + 1) |
                      getbit(pb, c00 + tprev) | getbit(pb, c00 + tprev + 1);
                int i = ty * t + li, j = tx * t + lj;
                lin = i * (2048 >> L) + j;
                pw = (i << 16) | j;
            }
            emit(L, act, lin, pw, c_IOFS[L], (L < 7) ? (bits[L] + r * 32) : nullptr);
        }
    }
}

// ---- levels 8..13, single block --------------------------------------------
__global__ __launch_bounds__(1024) void build_top() {
    int tid = threadIdx.x;
    for (int k = 8; k < NLEV; k++) {
        int s = c_LS[k], sp = c_LS[k - 1];
        int cells = s * s;
        const int* Ip = g_idx + c_IOFS[k - 1];
        bool act = false;
        int lin = -1, pw = 0;
        if (tid < cells) {
            int i = tid / s, j = tid - i * s;
            #pragma unroll
            for (int di = 0; di < 2; di++)
                #pragma unroll
                for (int dj = 0; dj < 2; dj++) {
                    int r = 2 * i + di, cc = 2 * j + dj;
                    if (r < sp && cc < sp && Ip[r * sp + cc] >= 0) act = true;
                }
            lin = tid;
            pw = (i << 16) | j;
        }
        emit(k, act, lin, pw, c_IOFS[k], nullptr);
    }
}

// ---- level-0 conv: 5x5, cin=1 -> 32 ----------------------------------------
__global__ void conv1_kernel(const float* __restrict__ x, const float* __restrict__ w1) {
    __shared__ float sw[800];
    __shared__ float bsum[32];
    int tid = threadIdx.x;
    for (int t = tid; t < 800; t += 256) sw[t] = w1[t];
    if (tid < 32) bsum[tid] = 0.f;
    __syncthreads();

    int n = min(g_cnt[0], CAP);
    int lane = tid & 31;
    int gw = (blockIdx.x * 256 + tid) >> 5;
    int nw = (gridDim.x * 256) >> 5;
    float pool = 0.f;
    for (int p = gw; p < n; p += nw) {
        int pw = g_pos[p];
        int i = pw >> 16, j = pw & 0xffff;
        float acc = 0.f;
        #pragma unroll
        for (int dy = 0; dy < 5; dy++) {
            int r = i + dy - 2;
            if ((unsigned)r < 2048u) {
                #pragma unroll
                for (int dx = 0; dx < 5; dx++) {
                    int cc = j + dx - 2;
                    if ((unsigned)cc < 2048u)
                        acc = fmaf(x[r * 2048 + cc], sw[(dy * 5 + dx) * 32 + lane], acc);
                }
            }
        }
        acc = fmaxf(acc, 0.f);
        g_FA[(size_t)p * 32 + lane] = acc;
        pool += acc;
    }
    atomicAdd(&bsum[lane], pool);
    __syncthreads();
    if (tid < 32) atomicAdd(&g_pools[tid], bsum[tid]);
}

// ---- levels 1..7: sparse tile-GEMM with f32x2 packed FMA -------------------
// smem: sW 9216 f | sA2 8192 f (activation, duplicated pairs) | sNbr 1152 i | spool 32 f
#define CONVK_SMEM ((9216 + 8192) * 4 + 1152 * 4 + 32 * 4)

__global__ __launch_bounds__(256) void convk_kernel(const float* __restrict__ ws,
                                                    int level, int sprev, int iofs_prev) {
    extern __shared__ float smem[];
    float* sW   = smem;                       // [9][32][32]
    float* sA2  = smem + 9216;                // [ci][256] : value duplicated pairs
    int*   sNbr = (int*)(smem + 9216 + 8192); // [9][128]
    float* spool = (float*)(sNbr + 9 * 128);  // [32]

    const float* Fprev;
    float* Fcur;
    if (level & 1) { Fprev = g_FA; Fcur = g_FB; }
    else           { Fprev = g_FB; Fcur = g_FA; }

    int tid = threadIdx.x;
    {
        const float4* wsrc = (const float4*)(ws + (size_t)(level - 1) * 9216);
        float4* wdst = (float4*)sW;
        for (int t = tid; t < 2304; t += 256) wdst[t] = wsrc[t];
    }
    if (tid < 32) spool[tid] = 0.f;
    __syncthreads();

    int n = min(g_cnt[level], CAP);
    const int* posl = g_pos + level * CAP;
    const int* Iprev = g_idx + iofs_prev;

    int ch = (tid & 7) * 4;        // 4 output channels
    int pb = (tid >> 3) * 4;       // 4 consecutive positions
    float pl0 = 0.f, pl1 = 0.f, pl2 = 0.f, pl3 = 0.f;

    for (int base = blockIdx.x * 128; base < n; base += gridDim.x * 128) {
        __syncthreads();
        if (tid < 128) {
            int p = base + tid;
            if (p < n) {
                int pw = posl[p];
                int pi = pw >> 16, pj = pw & 0xffff;
                #pragma unroll
                for (int d = 0; d < 9; d++) {
                    int r = 2 * pi + d / 3 - 1;
                    int cc = 2 * pj + d % 3 - 1;
                    int nb = -1;
                    if ((unsigned)r < (unsigned)sprev && (unsigned)cc < (unsigned)sprev)
                        nb = Iprev[r * sprev + cc];
                    sNbr[d * 128 + tid] = nb;
                }
            } else {
                #pragma unroll
                for (int d = 0; d < 9; d++) sNbr[d * 128 + tid] = -1;
            }
        }
        unsigned long long acc[4][2] = {{0ull,0ull},{0ull,0ull},{0ull,0ull},{0ull,0ull}};

        for (int d = 0; d < 9; d++) {
            int any = __syncthreads_or((tid < 128) ? (sNbr[d * 128 + tid] >= 0) : 0);
            if (!any) continue;
            // gather: duplicated pairs (v,v) -> sA2[ci][2*row]
            {
                int row = tid >> 1;
                int cb = (tid & 1) * 16;
                int nb = sNbr[d * 128 + row];
                if (nb >= 0) {
                    const float4* src = (const float4*)(Fprev + (size_t)nb * 32 + cb);
                    #pragma unroll
                    for (int q = 0; q < 4; q++) {
                        float4 v = src[q];
                        int ci = cb + q * 4;
                        *(float2*)&sA2[(ci + 0) * 256 + 2 * row] = make_float2(v.x, v.x);
                        *(float2*)&sA2[(ci + 1) * 256 + 2 * row] = make_float2(v.y, v.y);
                        *(float2*)&sA2[(ci + 2) * 256 + 2 * row] = make_float2(v.z, v.z);
                        *(float2*)&sA2[(ci + 3) * 256 + 2 * row] = make_float2(v.w, v.w);
                    }
                } else {
                    #pragma unroll
                    for (int q = 0; q < 16; q++)
                        *(float2*)&sA2[(cb + q) * 256 + 2 * row] = make_float2(0.f, 0.f);
                }
            }
            __syncthreads();
            const float* wd = sW + d * 1024;
            #pragma unroll
            for (int ci = 0; ci < 32; ci++) {
                unsigned long long w0 = *(const unsigned long long*)(wd + ci * 32 + ch);
                unsigned long long w1 = *(const unsigned long long*)(wd + ci * 32 + ch + 2);
                const float* sa = sA2 + ci * 256 + 2 * pb;
                unsigned long long v0 = *(const unsigned long long*)(sa);
                unsigned long long v1 = *(const unsigned long long*)(sa + 2);
                unsigned long long v2 = *(const unsigned long long*)(sa + 4);
                unsigned long long v3 = *(const unsigned long long*)(sa + 6);
                FMA2(acc[0][0], v0, w0, acc[0][0]); FMA2(acc[0][1], v0, w1, acc[0][1]);
                FMA2(acc[1][0], v1, w0, acc[1][0]); FMA2(acc[1][1], v1, w1, acc[1][1]);
                FMA2(acc[2][0], v2, w0, acc[2][0]); FMA2(acc[2][1], v2, w1, acc[2][1]);
                FMA2(acc[3][0], v3, w0, acc[3][0]); FMA2(acc[3][1], v3, w1, acc[3][1]);
            }
        }
        #pragma unroll
        for (int q = 0; q < 4; q++) {
            int p = base + pb + q;
            if (p < n) {
                float2 a0 = upk(acc[q][0]);
                float2 a1 = upk(acc[q][1]);
                float4 v;
                v.x = fmaxf(a0.x, 0.f);
                v.y = fmaxf(a0.y, 0.f);
                v.z = fmaxf(a1.x, 0.f);
                v.w = fmaxf(a1.y, 0.f);
                *(float4*)(Fcur + (size_t)p * 32 + ch) = v;
                pl0 += v.x; pl1 += v.y; pl2 += v.z; pl3 += v.w;
            }
        }
    }
    pl0 += __shfl_xor_sync(0xffffffffu, pl0, 8); pl0 += __shfl_xor_sync(0xffffffffu, pl0, 16);
    pl1 += __shfl_xor_sync(0xffffffffu, pl1, 8); pl1 += __shfl_xor_sync(0xffffffffu, pl1, 16);
    pl2 += __shfl_xor_sync(0xffffffffu, pl2, 8); pl2 += __shfl_xor_sync(0xffffffffu, pl2, 16);
    pl3 += __shfl_xor_sync(0xffffffffu, pl3, 8); pl3 += __shfl_xor_sync(0xffffffffu, pl3, 16);
    if ((tid & 31) < 8) {
        atomicAdd(&spool[ch + 0], pl0);
        atomicAdd(&spool[ch + 1], pl1);
        atomicAdd(&spool[ch + 2], pl2);
        atomicAdd(&spool[ch + 3], pl3);
    }
    __syncthreads();
    if (tid < 32) atomicAdd(&g_pools[level * 32 + tid], spool[tid]);
}

// ---- tail: levels 8..13 convs + pools + MLP, single block ------------------
__global__ __launch_bounds__(256) void tail_kernel(
    const float* __restrict__ ws,
    const float* __restrict__ wm1, const float* __restrict__ bm1,
    const float* __restrict__ wm2, const float* __restrict__ bm2,
    float* __restrict__ out) {
    __shared__ float spool[32];
    int tid = threadIdx.x, wid = tid >> 5, lane = tid & 31;

    for (int k = 8; k < NLEV; k++) {
        int n = min(g_cnt[k], CAP);
        int sp = c_LS[k - 1];
        const int* Ip = g_idx + c_IOFS[k - 1];
        const float* Fp = (k & 1) ? g_FA : g_FB;
        float* Fc = (k & 1) ? g_FB : g_FA;
        const float* W = ws + (size_t)(k - 1) * 9216;
        if (tid < 32) spool[tid] = 0.f;
        __syncthreads();
        float pool = 0.f;
        for (int p = wid; p < n; p += 8) {
            int pw = g_pos[k * CAP + p];
            int pi = pw >> 16, pj = pw & 0xffff;
            float acc = 0.f;
            for (int d = 0; d < 9; d++) {
                int r = 2 * pi + d / 3 - 1;
                int cc = 2 * pj + d % 3 - 1;
                if ((unsigned)r < (unsigned)sp && (unsigned)cc < (unsigned)sp) {
                    int nb = Ip[r * sp + cc];
                    if (nb >= 0) {
                        float row = Fp[(size_t)nb * 32 + lane];
                        const float* wd = W + d * 1024;
                        #pragma unroll
                        for (int ci = 0; ci < 32; ci++)
                            acc = fmaf(__shfl_sync(0xffffffffu, row, ci),
                                       wd[ci * 32 + lane], acc);
                    }
                }
            }
            acc = fmaxf(acc, 0.f);
            Fc[(size_t)p * 32 + lane] = acc;
            pool += acc;
        }
        atomicAdd(&spool[lane], pool);
        __syncthreads();
        if (tid < 32) g_pools[k * 32 + tid] = spool[tid];
        __syncthreads();
    }

    // MLP: feat[448] -> 256 relu -> 128
    __shared__ float sf[448];
    __shared__ float sh[256];
    for (int i = tid; i < 448; i += 256) {
        int k = i >> 5;
        float cnt = (float)max(g_cnt[k], 1);
        sf[i] = g_pools[i] / cnt;
    }
    __syncthreads();
    {
        float acc = bm1[tid];
        #pragma unroll 4
        for (int i = 0; i < 448; i++) acc = fmaf(sf[i], wm1[i * 256 + tid], acc);
        sh[tid] = fmaxf(acc, 0.f);
    }
    __syncthreads();
    if (tid < 128) {
        float acc = bm2[tid];
        #pragma unroll 4
        for (int j = 0; j < 256; j++) acc = fmaf(sh[j], wm2[j * 128 + tid], acc);
        out[tid] = acc;
    }
}

// ---- host launch -------------------------------------------------------------
static const int H_LS[NLEV]   = {2048,1024,512,256,128,64,32,16,8,4,2,1,1,1};
static const int H_IOFS[NLEV] = {0,4194304,5242880,5505024,5570560,5586944,5591040,
                                 5592064,5592320,5592384,5592400,5592404,5592405,5592406};

extern "C" void kernel_launch(void* const* d_in, const int* in_sizes, int n_in,
                              void* d_out, int out_size) {
    const float* x    = (const float*)d_in[0];
    const float* mask = (const float*)d_in[1];
    const float* w1   = (const float*)d_in[2];
    const float* ws   = (const float*)d_in[3];
    const float* wm1  = (const float*)d_in[4];
    const float* bm1  = (const float*)d_in[5];
    const float* wm2  = (const float*)d_in[6];
    const float* bm2  = (const float*)d_in[7];
    float* out = (float*)d_out;

    cudaFuncSetAttribute((const void*)convk_kernel,
                         cudaFuncAttributeMaxDynamicSharedMemorySize, CONVK_SMEM);

    void* cnt_ptr = nullptr;
    void* pools_ptr = nullptr;
    cudaGetSymbolAddress(&cnt_ptr, g_cnt);
    cudaGetSymbolAddress(&pools_ptr, g_pools);
    cudaMemsetAsync(cnt_ptr, 0, NLEV * sizeof(int));
    cudaMemsetAsync(pools_ptr, 0, NLEV * 32 * sizeof(float));

    build_all0<<<256, 1024>>>(mask);
    build_top<<<1, 1024>>>();

    conv1_kernel<<<1024, 256>>>(x, w1);

    static const int cgrid[8] = {0, 444, 444, 444, 128, 32, 8, 2};
    for (int k = 1; k <= 7; k++)
        convk_kernel<<<cgrid[k], 256, CONVK_SMEM>>>(ws, k, H_LS[k - 1], H_IOFS[k - 1]);

    tail_kernel<<<1, 256>>>(ws, wm1, bm1, wm2, bm2, out);
}